// round 15
// baseline (speedup 1.0000x reference)
#include <cuda_runtime.h>
#include <cuda_fp16.h>
#include <cstdint>

#define NS 512
#define NK 64
#define NVEC 65536
#define M_TILE 128
#define NCTA (NVEC / M_TILE)      /* 512 */
#define NTHR 384                  /* 8 HMMA warps + 4 FFMA warps */
#define CH 320                    /* codes handled by HMMA (5 tiles) */
#define NT_H 5                    /* HMMA tiles */

#define OFF_Z      (NVEC*NK)
#define OFF_COMMIT (OFF_Z + NVEC)
#define OFF_CB     (OFF_COMMIT + 1)
#define OFF_ERR    (OFF_CB + 1)

/* smem: A region [0,32768) reused as 2x16KB B double-buffer */
#define SM_A    0
#define SM_B    0
#define SM_SCN  32768       /* 512*4 */
#define SM_VN   34816       /* 128*4 */
#define SM_FS   35328       /* 128*4 FFMA best score */
#define SM_FI   35840       /* 128*4 FFMA best idx */
#define SM_RED  36352       /* 8*4 */
#define SM_TOT  36480

typedef unsigned long long u64;

__device__ float  g_c[NS * NK];
__device__ float  g_cnh[NS];
__device__ __half g_ch[2][NS * NK];      // codebook fp16 planes (h0, h1)
__device__ float  g_partial[NCTA];
__device__ int    g_done;

__device__ __forceinline__ uint32_t smem_u32(const void* p) {
    uint32_t a;
    asm("{ .reg .u64 t; cvta.to.shared.u64 t, %1; cvt.u32.u64 %0, t; }" : "=r"(a) : "l"(p));
    return a;
}
__device__ __forceinline__ void ldsm_x4(uint32_t* r, uint32_t a) {
    asm volatile("ldmatrix.sync.aligned.m8n8.x4.shared.b16 {%0,%1,%2,%3}, [%4];"
                 : "=r"(r[0]), "=r"(r[1]), "=r"(r[2]), "=r"(r[3]) : "r"(a));
}
__device__ __forceinline__ void mma_f32(float* c, const uint32_t* a, const uint32_t* b) {
    asm volatile("mma.sync.aligned.m16n8k16.row.col.f32.f16.f16.f32 "
                 "{%0,%1,%2,%3}, {%4,%5,%6,%7}, {%8,%9}, {%0,%1,%2,%3};"
                 : "+f"(c[0]), "+f"(c[1]), "+f"(c[2]), "+f"(c[3])
                 : "r"(a[0]), "r"(a[1]), "r"(a[2]), "r"(a[3]), "r"(b[0]), "r"(b[1]));
}
__device__ __forceinline__ void cpa16(uint32_t dst, const void* src) {
    asm volatile("cp.async.cg.shared.global [%0], [%1], 16;" :: "r"(dst), "l"(src));
}
#define CPA_COMMIT() asm volatile("cp.async.commit_group;" ::: "memory")
#define CPA_WAIT(n)  asm volatile("cp.async.wait_group %0;" :: "n"(n) : "memory")
#define BAR1() asm volatile("bar.sync 1, 256;" ::: "memory")

__device__ __forceinline__ u64 fma2(u64 a, u64 b, u64 c) {
    u64 d;
    asm("fma.rn.f32x2 %0, %1, %2, %3;" : "=l"(d) : "l"(a), "l"(b), "l"(c));
    return d;
}
__device__ __forceinline__ u64 add2(u64 a, u64 b) {
    u64 d;
    asm("add.rn.f32x2 %0, %1, %2;" : "=l"(d) : "l"(a), "l"(b));
    return d;
}
__device__ __forceinline__ float hsum2(u64 a) {
    float lo, hi;
    asm("mov.b64 {%0, %1}, %2;" : "=f"(lo), "=f"(hi) : "l"(a));
    return lo + hi;
}
__device__ __forceinline__ u64 pk2(float lo, float hi) {
    u64 d;
    asm("mov.b64 %0, {%1, %2};" : "=l"(d) : "f"(lo), "f"(hi));
    return d;
}
__device__ __forceinline__ void hsplit(float x, __half& h0, __half& h1) {
    h0 = __float2half_rn(x);
    h1 = __float2half_rn(x - __half2float(h0));
}

// ---------------------------------------------------------------------------
// Kernel 1: codebook -> fp32 + half-norms + fp16 planes; reset done counter.
// ---------------------------------------------------------------------------
__global__ void __launch_bounds__(128) vq_prep_code(const float* __restrict__ c_sum,
                                                    const float* __restrict__ c_count) {
    if (blockIdx.x == 0 && threadIdx.x == 0) g_done = 0;
    int warp = (blockIdx.x * blockDim.x + threadIdx.x) >> 5;
    int lane = threadIdx.x & 31;
    if (warp >= NS) return;
    float inv = 1.0f / fmaxf(c_count[warp], 0.01f);
    float a = c_sum[warp * NK + lane] * inv;
    float b = c_sum[warp * NK + 32 + lane] * inv;
    g_c[warp * NK + lane] = a;
    g_c[warp * NK + 32 + lane] = b;
    __half h0, h1;
    hsplit(a, h0, h1);
    g_ch[0][warp * NK + lane] = h0;
    g_ch[1][warp * NK + lane] = h1;
    hsplit(b, h0, h1);
    g_ch[0][warp * NK + 32 + lane] = h0;
    g_ch[1][warp * NK + 32 + lane] = h1;
    float nh = a * a + b * b;
#pragma unroll
    for (int o = 16; o; o >>= 1) nh += __shfl_xor_sync(0xffffffffu, nh, o);
    if (lane == 0) g_cnh[warp] = 0.5f * nh;
}

// ---------------------------------------------------------------------------
// Kernel 2: dual-pipe search. Warps 0-7: 3-term HMMA over codes 0-319.
// Warps 8-11: exact fp32 FFMA2 over codes 320-511 (one row per lane).
// ---------------------------------------------------------------------------
__global__ void __launch_bounds__(NTHR, 2) vq_mma(const float* __restrict__ vecs,
                                                  float* __restrict__ out) {
    extern __shared__ __align__(128) char smem[];
    uint32_t sb = smem_u32(smem);
    int tid = threadIdx.x;
    int wid = tid >> 5;
    int lane = tid & 31;
    int cta = blockIdx.x;

    float best[2] = {-3.4e38f, -3.4e38f};
    int idx[2] = {0, 0};

    if (tid < 256) {
        // ---------------- HMMA path (warps 0-7) ----------------
        for (int i = tid; i < NS; i += 256)
            reinterpret_cast<float*>(smem + SM_SCN)[i] = g_cnh[i];

        // A conversion: thread pair (2t, 2t+1) owns vector row t
        {
            int row = tid >> 1;
            int half = tid & 1;
            const float4* src = reinterpret_cast<const float4*>(
                vecs + ((size_t)cta * M_TILE + row) * NK) + half * 8;
            float vn = 0.f;
            int rsw = row & 7;
#pragma unroll
            for (int c = 0; c < 4; c++) {
                int ch = half * 4 + c;
                float4 q0 = src[2 * c], q1 = src[2 * c + 1];
                float x[8] = {q0.x, q0.y, q0.z, q0.w, q1.x, q1.y, q1.z, q1.w};
                union { uint4 u; __half2 h[4]; } p0, p1;
#pragma unroll
                for (int j = 0; j < 4; j++) {
                    __half a0, a1, b0, b1;
                    hsplit(x[2 * j], a0, a1);
                    hsplit(x[2 * j + 1], b0, b1);
                    p0.h[j] = __halves2half2(a0, b0);
                    p1.h[j] = __halves2half2(a1, b1);
                    vn += x[2 * j] * x[2 * j] + x[2 * j + 1] * x[2 * j + 1];
                }
                uint32_t off = row * 128 + ((ch ^ rsw) << 4);
                *reinterpret_cast<uint4*>(smem + SM_A + off) = p0.u;
                *reinterpret_cast<uint4*>(smem + SM_A + 16384 + off) = p1.u;
            }
            vn += __shfl_xor_sync(0xffffffffu, vn, 1);
            if (half == 0) reinterpret_cast<float*>(smem + SM_VN)[row] = vn;
        }
        BAR1();

        uint32_t af[2][4][4];
        {
            int r = lane & 15;
            int hi = lane >> 4;
#pragma unroll
            for (int p = 0; p < 2; p++) {
                int row = wid * 16 + r;
#pragma unroll
                for (int k = 0; k < 4; k++) {
                    int ch = (2 * k + hi) ^ (row & 7);
                    ldsm_x4(af[p][k], sb + SM_A + p * 16384 + row * 128 + ch * 16);
                }
            }
        }
        BAR1();   // A region becomes B double-buffer

        auto loadB = [&](int tile, int buf) {
#pragma unroll
            for (int j = 0; j < 4; j++) {
                int i = tid + 256 * j;
                int row = i >> 3, ch = i & 7;
                int p = row >> 6, r = row & 63;
                const __half* src = g_ch[p] + ((size_t)tile * 64 + r) * NK + ch * 8;
                cpa16(sb + SM_B + buf * 16384 + p * 8192 + r * 128 + (((ch ^ (r & 7))) << 4), src);
            }
        };
        loadB(0, 0);
        CPA_COMMIT();

        const float* scn = reinterpret_cast<const float*>(smem + SM_SCN);
        int brow_lo = (lane >> 4) << 3;
        int kh = (lane >> 3) & 1;

        for (int tile = 0; tile < NT_H; tile++) {
            if (tile < NT_H - 1) { loadB(tile + 1, (tile + 1) & 1); CPA_COMMIT(); CPA_WAIT(1); }
            else CPA_WAIT(0);
            BAR1();
            uint32_t bbase = sb + SM_B + (tile & 1) * 16384;

#pragma unroll
            for (int npair = 0; npair < 4; npair++) {
                float acc[2][4] = {};
                int row = npair * 16 + brow_lo + (lane & 7);
                int rsw = row & 7;
#pragma unroll
                for (int k = 0; k < 4; k++) {     // plane 0: a0 + a1 terms
                    uint32_t bf[4];
                    ldsm_x4(bf, bbase + row * 128 + (((2 * k + kh) ^ rsw) << 4));
                    mma_f32(acc[0], af[0][k], bf + 0);
                    mma_f32(acc[1], af[0][k], bf + 2);
                    mma_f32(acc[0], af[1][k], bf + 0);
                    mma_f32(acc[1], af[1][k], bf + 2);
                }
#pragma unroll
                for (int k = 0; k < 4; k++) {     // plane 1: a0 term only
                    uint32_t bf[4];
                    ldsm_x4(bf, bbase + 8192 + row * 128 + (((2 * k + kh) ^ rsw) << 4));
                    mma_f32(acc[0], af[0][k], bf + 0);
                    mma_f32(acc[1], af[0][k], bf + 2);
                }
#pragma unroll
                for (int nb = 0; nb < 2; nb++) {
                    int ncol = tile * 64 + npair * 16 + nb * 8 + 2 * (lane & 3);
                    float s0 = scn[ncol], s1 = scn[ncol + 1];
                    float v;
                    v = acc[nb][0] - s0; if (v > best[0]) { best[0] = v; idx[0] = ncol; }
                    v = acc[nb][1] - s1; if (v > best[0]) { best[0] = v; idx[0] = ncol + 1; }
                    v = acc[nb][2] - s0; if (v > best[1]) { best[1] = v; idx[1] = ncol; }
                    v = acc[nb][3] - s1; if (v > best[1]) { best[1] = v; idx[1] = ncol + 1; }
                }
            }
            BAR1();
        }

        // quad reduce (tie -> lower index)
#pragma unroll
        for (int slot = 0; slot < 2; slot++) {
#pragma unroll
            for (int off = 1; off <= 2; off <<= 1) {
                float ob = __shfl_xor_sync(0xffffffffu, best[slot], off);
                int oi = __shfl_xor_sync(0xffffffffu, idx[slot], off);
                if (ob > best[slot] || (ob == best[slot] && oi < idx[slot])) {
                    best[slot] = ob; idx[slot] = oi;
                }
            }
        }
    } else {
        // ---------------- FFMA path (warps 8-11), codes 320-511, exact fp32 --
        int row = (wid - 8) * 32 + lane;              // 0..127
        const float4* src = reinterpret_cast<const float4*>(
            vecs + ((size_t)cta * M_TILE + row) * NK);
        u64 vp[32];
#pragma unroll
        for (int i = 0; i < 16; i++) {
            float4 q = src[i];
            vp[2 * i]     = pk2(q.x, q.y);
            vp[2 * i + 1] = pk2(q.z, q.w);
        }
        float fb = -3.4e38f;
        int fi = CH;
        for (int s = CH; s < NS; s++) {
            const float4* cb = reinterpret_cast<const float4*>(g_c + (size_t)s * NK);
            u64 a0 = 0, a1 = 0, a2 = 0, a3 = 0;
#pragma unroll
            for (int i = 0; i < 8; i++) {
                float4 q0 = __ldg(cb + 2 * i);
                float4 q1 = __ldg(cb + 2 * i + 1);
                a0 = fma2(vp[4 * i + 0], pk2(q0.x, q0.y), a0);
                a1 = fma2(vp[4 * i + 1], pk2(q0.z, q0.w), a1);
                a2 = fma2(vp[4 * i + 2], pk2(q1.x, q1.y), a2);
                a3 = fma2(vp[4 * i + 3], pk2(q1.z, q1.w), a3);
            }
            float sc = hsum2(add2(add2(a0, a1), add2(a2, a3))) - __ldg(&g_cnh[s]);
            if (sc > fb) { fb = sc; fi = s; }
        }
        reinterpret_cast<float*>(smem + SM_FS)[row] = fb;
        reinterpret_cast<int*>(smem + SM_FI)[row] = fi;
    }

    __syncthreads();   // all 384: FFMA results + svn visible

    if (tid < 256) {
        const float* svn = reinterpret_cast<const float*>(smem + SM_VN);
        const float* fs = reinterpret_cast<const float*>(smem + SM_FS);
        const int*   fixv = reinterpret_cast<const int*>(smem + SM_FI);
        float errsum = 0.f;
#pragma unroll
        for (int slot = 0; slot < 2; slot++) {
            int row = wid * 16 + slot * 8 + (lane >> 2);
            // merge FFMA winner (codes > CH: strict > keeps first-min ties)
            float fsc = fs[row];
            if (fsc > best[slot]) { best[slot] = fsc; idx[slot] = fixv[row]; }
            int n = cta * M_TILE + row;
            const float4* c = reinterpret_cast<const float4*>(g_c + (size_t)idx[slot] * NK);
            float4* o = reinterpret_cast<float4*>(out + (size_t)n * NK);
#pragma unroll
            for (int j = lane & 3; j < 16; j += 4) o[j] = c[j];
            if ((lane & 3) == 0) {
                float err = fmaxf(svn[row] - 2.0f * best[slot], 0.0f);
                out[OFF_Z + n] = (float)idx[slot];
                out[OFF_ERR + n] = err;
                errsum += err;
            }
        }
#pragma unroll
        for (int o = 16; o; o >>= 1) errsum += __shfl_xor_sync(0xffffffffu, errsum, o);
        if (lane == 0) reinterpret_cast<float*>(smem + SM_RED)[wid] = errsum;
    }
    __syncthreads();
    if (tid == 0) {
        const float* red = reinterpret_cast<const float*>(smem + SM_RED);
        g_partial[cta] = ((red[0] + red[1]) + (red[2] + red[3]))
                       + ((red[4] + red[5]) + (red[6] + red[7]));
    }

    // fused finalize: last CTA reduces all partials (fixed deterministic order)
    __shared__ int s_last;
    if (tid == 0) {
        __threadfence();
        s_last = (atomicAdd(&g_done, 1) == NCTA - 1);
    }
    __syncthreads();
    if (s_last) {
        __threadfence();
        float* fred = reinterpret_cast<float*>(smem + SM_A);
        if (tid < 256) fred[tid] = g_partial[tid] + g_partial[tid + 256];
        __syncthreads();
#pragma unroll
        for (int off = 128; off > 0; off >>= 1) {
            if (tid < off) fred[tid] += fred[tid + off];
            __syncthreads();
        }
        if (tid == 0) {
            out[OFF_COMMIT] = fred[0] * (1.0f / (float)NVEC);
            out[OFF_CB] = 0.0f;   // l_codebook is identically 0 in forward value
        }
    }
}

extern "C" void kernel_launch(void* const* d_in, const int* in_sizes, int n_in,
                              void* d_out, int out_size) {
    const float* vecs    = (const float*)d_in[0];
    const float* c_sum   = (const float*)d_in[1];
    const float* c_count = (const float*)d_in[2];
    float* out = (float*)d_out;

    cudaFuncSetAttribute(vq_mma, cudaFuncAttributeMaxDynamicSharedMemorySize, SM_TOT);

    vq_prep_code<<<128, 128>>>(c_sum, c_count);
    vq_mma<<<NCTA, NTHR, SM_TOT>>>(vecs, out);
}

// round 17
// speedup vs baseline: 4.1766x; 4.1766x over previous
#include <cuda_runtime.h>
#include <cuda_fp16.h>
#include <cstdint>

#define NS 512
#define NK 64
#define NVEC 65536
#define M_TILE 256
#define NCTA (NVEC / M_TILE)      /* 256 */
#define NTHR 256
#define NT_H 7                    /* HMMA tiles: codes 0-447 */
#define CF 448                    /* first FFMA code */

#define OFF_Z      (NVEC*NK)
#define OFF_COMMIT (OFF_Z + NVEC)
#define OFF_CB     (OFF_COMMIT + 1)
#define OFF_ERR    (OFF_CB + 1)

/* smem: a0 plane [0,32768) -> B ring after prologue; a1 plane resident. */
#define SM_A    0
#define SM_B    0
#define SM_A1   32768
#define SM_SCN  65536       /* 512*4 */
#define SM_VN   67584       /* 256*4 */
#define SM_FS   68608       /* 256*4 FFMA best score */
#define SM_FI   69632       /* 256*4 FFMA best idx  */
#define SM_RED  70656       /* 8*4 */
#define SM_TOT  70720

typedef unsigned long long u64;

__device__ float  g_c[NS * NK];
__device__ float  g_cnh[NS];
__device__ __half g_ch[2][NS * NK];      // codebook fp16 planes (h0, h1)
__device__ float  g_partial[NCTA];
__device__ int    g_done;

__device__ __forceinline__ uint32_t smem_u32(const void* p) {
    uint32_t a;
    asm("{ .reg .u64 t; cvta.to.shared.u64 t, %1; cvt.u32.u64 %0, t; }" : "=r"(a) : "l"(p));
    return a;
}
__device__ __forceinline__ void ldsm_x4(uint32_t* r, uint32_t a) {
    asm volatile("ldmatrix.sync.aligned.m8n8.x4.shared.b16 {%0,%1,%2,%3}, [%4];"
                 : "=r"(r[0]), "=r"(r[1]), "=r"(r[2]), "=r"(r[3]) : "r"(a));
}
__device__ __forceinline__ void mma_f32(float* c, const uint32_t* a, const uint32_t* b) {
    asm volatile("mma.sync.aligned.m16n8k16.row.col.f32.f16.f16.f32 "
                 "{%0,%1,%2,%3}, {%4,%5,%6,%7}, {%8,%9}, {%0,%1,%2,%3};"
                 : "+f"(c[0]), "+f"(c[1]), "+f"(c[2]), "+f"(c[3])
                 : "r"(a[0]), "r"(a[1]), "r"(a[2]), "r"(a[3]), "r"(b[0]), "r"(b[1]));
}
__device__ __forceinline__ void cpa16(uint32_t dst, const void* src) {
    asm volatile("cp.async.cg.shared.global [%0], [%1], 16;" :: "r"(dst), "l"(src));
}
#define CPA_COMMIT() asm volatile("cp.async.commit_group;" ::: "memory")
#define CPA_WAIT(n)  asm volatile("cp.async.wait_group %0;" :: "n"(n) : "memory")

__device__ __forceinline__ u64 fma2(u64 a, u64 b, u64 c) {
    u64 d;
    asm("fma.rn.f32x2 %0, %1, %2, %3;" : "=l"(d) : "l"(a), "l"(b), "l"(c));
    return d;
}
__device__ __forceinline__ u64 add2(u64 a, u64 b) {
    u64 d;
    asm("add.rn.f32x2 %0, %1, %2;" : "=l"(d) : "l"(a), "l"(b));
    return d;
}
__device__ __forceinline__ float hsum2(u64 a) {
    float lo, hi;
    asm("mov.b64 {%0, %1}, %2;" : "=f"(lo), "=f"(hi) : "l"(a));
    return lo + hi;
}
__device__ __forceinline__ void hsplit(float x, __half& h0, __half& h1) {
    h0 = __float2half_rn(x);
    h1 = __float2half_rn(x - __half2float(h0));
}

// ---------------------------------------------------------------------------
// Kernel 1: codebook -> fp32 + half-norms + fp16 planes; reset done counter.
// ---------------------------------------------------------------------------
__global__ void __launch_bounds__(128) vq_prep_code(const float* __restrict__ c_sum,
                                                    const float* __restrict__ c_count) {
    if (blockIdx.x == 0 && threadIdx.x == 0) g_done = 0;
    int warp = (blockIdx.x * blockDim.x + threadIdx.x) >> 5;
    int lane = threadIdx.x & 31;
    if (warp >= NS) return;
    float inv = 1.0f / fmaxf(c_count[warp], 0.01f);
    float a = c_sum[warp * NK + lane] * inv;
    float b = c_sum[warp * NK + 32 + lane] * inv;
    g_c[warp * NK + lane] = a;
    g_c[warp * NK + 32 + lane] = b;
    __half h0, h1;
    hsplit(a, h0, h1);
    g_ch[0][warp * NK + lane] = h0;
    g_ch[1][warp * NK + lane] = h1;
    hsplit(b, h0, h1);
    g_ch[0][warp * NK + 32 + lane] = h0;
    g_ch[1][warp * NK + 32 + lane] = h1;
    float nh = a * a + b * b;
#pragma unroll
    for (int o = 16; o; o >>= 1) nh += __shfl_xor_sync(0xffffffffu, nh, o);
    if (lane == 0) g_cnh[warp] = 0.5f * nh;
}

// ---------------------------------------------------------------------------
// Kernel 2: dual-pipe. 8 warps: 3-term HMMA (codes 0-447, a1 fragments
// streamed from smem) + interleaved exact-fp32 FFMA2 (codes 448-511, one
// row per lane, FULL K=64 dot). Bit-identical HMMA accumulation to R10.
// ---------------------------------------------------------------------------
__global__ void __launch_bounds__(NTHR, 2) vq_mma(const float* __restrict__ vecs,
                                                  float* __restrict__ out) {
    extern __shared__ __align__(128) char smem[];
    uint32_t sb = smem_u32(smem);
    int tid = threadIdx.x;
    int wid = tid >> 5;
    int lane = tid & 31;
    int cta = blockIdx.x;

    for (int i = tid; i < NS; i += NTHR)
        reinterpret_cast<float*>(smem + SM_SCN)[i] = g_cnh[i];

    // fused A conversion: thread t owns vector row t (256 rows)
    {
        const float4* src = reinterpret_cast<const float4*>(
            vecs + ((size_t)cta * M_TILE + tid) * NK);
        float vn = 0.f;
        int rsw = tid & 7;
#pragma unroll
        for (int ch = 0; ch < 8; ch++) {
            float4 q0 = src[2 * ch], q1 = src[2 * ch + 1];
            float x[8] = {q0.x, q0.y, q0.z, q0.w, q1.x, q1.y, q1.z, q1.w};
            union { uint4 u; __half2 h[4]; } p0, p1;
#pragma unroll
            for (int j = 0; j < 4; j++) {
                __half a0, a1, b0, b1;
                hsplit(x[2 * j], a0, a1);
                hsplit(x[2 * j + 1], b0, b1);
                p0.h[j] = __halves2half2(a0, b0);
                p1.h[j] = __halves2half2(a1, b1);
                vn += x[2 * j] * x[2 * j] + x[2 * j + 1] * x[2 * j + 1];
            }
            uint32_t off = tid * 128 + ((ch ^ rsw) << 4);
            *reinterpret_cast<uint4*>(smem + SM_A + off) = p0.u;
            *reinterpret_cast<uint4*>(smem + SM_A1 + off) = p1.u;
        }
        reinterpret_cast<float*>(smem + SM_VN)[tid] = vn;
    }
    __syncthreads();

    // register-resident a0 fragments only: [mtile][kstep][4] (warp: 32 rows)
    uint32_t af0[2][4][4];
    int ar = lane & 15;
    int ahi = lane >> 4;
#pragma unroll
    for (int mt = 0; mt < 2; mt++) {
        int row = wid * 32 + mt * 16 + ar;
#pragma unroll
        for (int k = 0; k < 4; k++) {
            int ch = (2 * k + ahi) ^ (row & 7);
            ldsm_x4(af0[mt][k], sb + SM_A + row * 128 + ch * 16);
        }
    }
    // a1-fragment addressing (reloaded per k inside mainloop)
    uint32_t a1base[2];
    int a1sw[2];
#pragma unroll
    for (int mt = 0; mt < 2; mt++) {
        int row = wid * 32 + mt * 16 + ar;
        a1base[mt] = sb + SM_A1 + row * 128;
        a1sw[mt] = row & 7;
    }
    __syncthreads();   // a0 region becomes B double-buffer

    auto loadB = [&](int tile, int buf) {
#pragma unroll
        for (int j = 0; j < 4; j++) {
            int i = tid + NTHR * j;
            int row = i >> 3, ch = i & 7;
            int p = row >> 6, r = row & 63;
            const __half* src = g_ch[p] + ((size_t)tile * 64 + r) * NK + ch * 8;
            cpa16(sb + SM_B + buf * 16384 + p * 8192 + r * 128 + (((ch ^ (r & 7))) << 4), src);
        }
    };
    loadB(0, 0);
    CPA_COMMIT();

    const float* scn = reinterpret_cast<const float*>(smem + SM_SCN);
    float best[4] = {-3.4e38f, -3.4e38f, -3.4e38f, -3.4e38f};
    int idx[4] = {0, 0, 0, 0};
    float fbest = -3.4e38f;
    int fidx = CF;
    int brow_lo = (lane >> 4) << 3;
    int kh = (lane >> 3) & 1;
    const ulonglong2* vrow = reinterpret_cast<const ulonglong2*>(
        vecs + ((size_t)cta * M_TILE + tid) * NK);

    for (int tile = 0; tile < NT_H; tile++) {
        if (tile < NT_H - 1) { loadB(tile + 1, (tile + 1) & 1); CPA_COMMIT(); CPA_WAIT(1); }
        else CPA_WAIT(0);
        __syncthreads();
        uint32_t bbase = sb + SM_B + (tile & 1) * 16384;

#pragma unroll
        for (int npair = 0; npair < 4; npair++) {
            float acc[2][2][4] = {};          // [mtile][nbhalf][4]
            int row = npair * 16 + brow_lo + (lane & 7);
            int rsw = row & 7;
#pragma unroll
            for (int k = 0; k < 4; k++) {     // B plane 0: a0 + a1 terms
                uint32_t bf[4];
                ldsm_x4(bf, bbase + row * 128 + (((2 * k + kh) ^ rsw) << 4));
#pragma unroll
                for (int mt = 0; mt < 2; mt++) {
                    mma_f32(acc[mt][0], af0[mt][k], bf + 0);
                    mma_f32(acc[mt][1], af0[mt][k], bf + 2);
                    uint32_t a1f[4];
                    ldsm_x4(a1f, a1base[mt] + (((2 * k + ahi) ^ a1sw[mt]) << 4));
                    mma_f32(acc[mt][0], a1f, bf + 0);
                    mma_f32(acc[mt][1], a1f, bf + 2);
                }
            }
#pragma unroll
            for (int k = 0; k < 4; k++) {     // B plane 1: a0 term only
                uint32_t bf[4];
                ldsm_x4(bf, bbase + 8192 + row * 128 + (((2 * k + kh) ^ rsw) << 4));
#pragma unroll
                for (int mt = 0; mt < 2; mt++) {
                    mma_f32(acc[mt][0], af0[mt][k], bf + 0);
                    mma_f32(acc[mt][1], af0[mt][k], bf + 2);
                }
            }
#pragma unroll
            for (int mt = 0; mt < 2; mt++)
#pragma unroll
                for (int nb = 0; nb < 2; nb++) {
                    int ncol = tile * 64 + npair * 16 + nb * 8 + 2 * (lane & 3);
                    float s0 = scn[ncol], s1 = scn[ncol + 1];
                    float v;
                    v = acc[mt][nb][0] - s0;
                    if (v > best[2*mt])   { best[2*mt] = v;   idx[2*mt] = ncol; }
                    v = acc[mt][nb][1] - s1;
                    if (v > best[2*mt])   { best[2*mt] = v;   idx[2*mt] = ncol + 1; }
                    v = acc[mt][nb][2] - s0;
                    if (v > best[2*mt+1]) { best[2*mt+1] = v; idx[2*mt+1] = ncol; }
                    v = acc[mt][nb][3] - s1;
                    if (v > best[2*mt+1]) { best[2*mt+1] = v; idx[2*mt+1] = ncol + 1; }
                }
        }

        // interleaved FFMA2: exact fp32 scores (FULL K=64) for ~10 of codes
        // 448-511. v row is L1-resident; g_c is L2-hot.
        {
            int c0 = tile * 10;
            int c1 = c0 + 10 > 64 ? 64 : c0 + 10;
            for (int cc = c0; cc < c1; cc++) {
                int s = CF + cc;
                const ulonglong2* cp = reinterpret_cast<const ulonglong2*>(g_c + (size_t)s * NK);
                u64 a0 = 0, a1 = 0, a2 = 0, a3 = 0;
#pragma unroll
                for (int i = 0; i < 16; i += 2) {     // 16 ulonglong2 = 64 floats
                    ulonglong2 cv0 = cp[i],     vv0 = vrow[i];
                    ulonglong2 cv1 = cp[i + 1], vv1 = vrow[i + 1];
                    a0 = fma2(vv0.x, cv0.x, a0);
                    a1 = fma2(vv0.y, cv0.y, a1);
                    a2 = fma2(vv1.x, cv1.x, a2);
                    a3 = fma2(vv1.y, cv1.y, a3);
                }
                float sc = hsum2(add2(add2(a0, a1), add2(a2, a3))) - scn[s];
                if (sc > fbest) { fbest = sc; fidx = s; }
            }
        }
        __syncthreads();
    }

    // publish FFMA winner for this lane's row
    reinterpret_cast<float*>(smem + SM_FS)[tid] = fbest;
    reinterpret_cast<int*>(smem + SM_FI)[tid] = fidx;

    // quad reduce HMMA winners (tie -> lower index)
#pragma unroll
    for (int slot = 0; slot < 4; slot++) {
#pragma unroll
        for (int off = 1; off <= 2; off <<= 1) {
            float ob = __shfl_xor_sync(0xffffffffu, best[slot], off);
            int oi = __shfl_xor_sync(0xffffffffu, idx[slot], off);
            if (ob > best[slot] || (ob == best[slot] && oi < idx[slot])) {
                best[slot] = ob; idx[slot] = oi;
            }
        }
    }
    __syncthreads();

    const float* svn = reinterpret_cast<const float*>(smem + SM_VN);
    const float* fs = reinterpret_cast<const float*>(smem + SM_FS);
    const int*   fiv = reinterpret_cast<const int*>(smem + SM_FI);
    float errsum = 0.f;
#pragma unroll
    for (int slot = 0; slot < 4; slot++) {
        int row = wid * 32 + (slot >> 1) * 16 + (slot & 1) * 8 + (lane >> 2);
        // merge FFMA winner (codes >= CF: strict > keeps lower-index ties)
        float fsc = fs[row];
        if (fsc > best[slot]) { best[slot] = fsc; idx[slot] = fiv[row]; }
        int n = cta * M_TILE + row;
        const float4* c = reinterpret_cast<const float4*>(g_c + (size_t)idx[slot] * NK);
        float4* o = reinterpret_cast<float4*>(out + (size_t)n * NK);
#pragma unroll
        for (int j = lane & 3; j < 16; j += 4) o[j] = c[j];
        if ((lane & 3) == 0) {
            float err = fmaxf(svn[row] - 2.0f * best[slot], 0.0f);
            out[OFF_Z + n] = (float)idx[slot];
            out[OFF_ERR + n] = err;
            errsum += err;
        }
    }
#pragma unroll
    for (int o = 16; o; o >>= 1) errsum += __shfl_xor_sync(0xffffffffu, errsum, o);
    float* red = reinterpret_cast<float*>(smem + SM_RED);
    if (lane == 0) red[wid] = errsum;
    __syncthreads();
    if (tid == 0)
        g_partial[cta] = ((red[0] + red[1]) + (red[2] + red[3]))
                       + ((red[4] + red[5]) + (red[6] + red[7]));

    // fused finalize: last CTA reduces all partials (fixed deterministic order)
    __shared__ int s_last;
    if (tid == 0) {
        __threadfence();
        s_last = (atomicAdd(&g_done, 1) == NCTA - 1);
    }
    __syncthreads();
    if (s_last) {
        __threadfence();
        float* fred = reinterpret_cast<float*>(smem + SM_A);
        fred[tid] = g_partial[tid];
        __syncthreads();
#pragma unroll
        for (int off = 128; off > 0; off >>= 1) {
            if (tid < off) fred[tid] += fred[tid + off];
            __syncthreads();
        }
        if (tid == 0) {
            out[OFF_COMMIT] = fred[0] * (1.0f / (float)NVEC);
            out[OFF_CB] = 0.0f;   // l_codebook is identically 0 in forward value
        }
    }
}

extern "C" void kernel_launch(void* const* d_in, const int* in_sizes, int n_in,
                              void* d_out, int out_size) {
    const float* vecs    = (const float*)d_in[0];
    const float* c_sum   = (const float*)d_in[1];
    const float* c_count = (const float*)d_in[2];
    float* out = (float*)d_out;

    cudaFuncSetAttribute(vq_mma, cudaFuncAttributeMaxDynamicSharedMemorySize, SM_TOT);

    vq_prep_code<<<128, 128>>>(c_sum, c_count);
    vq_mma<<<NCTA, NTHR, SM_TOT>>>(vecs, out);
}